// round 1
// baseline (speedup 1.0000x reference)
#include <cuda_runtime.h>
#include <math.h>

#define S_LEN 2048
#define BATCH 2
#define DMODEL 1024
#define NH 16
#define NKV 4
#define DH 64
#define TOKENS (BATCH * S_LEN)   // 4096
#define KVDIM (NKV * DH)         // 256

// Scratch (device globals: no allocations allowed in kernel_launch)
__device__ float g_Q[TOKENS * DMODEL];     // 16 MB
__device__ float g_K[TOKENS * KVDIM];      //  4 MB
__device__ float g_V[TOKENS * KVDIM];      //  4 MB
__device__ float g_C[TOKENS * DMODEL];     // 16 MB

// ---------------------------------------------------------------------------
// Classic 128x128x8 register-tiled SGEMM. A: MxK row-major, B: KxN row-major.
// M % 128 == 0, N % 128 == 0, K % 8 == 0 (true for all four GEMMs here).
// ---------------------------------------------------------------------------
__global__ __launch_bounds__(256) void sgemm128(const float* __restrict__ A,
                                                const float* __restrict__ B,
                                                float* __restrict__ C,
                                                int M, int N, int K)
{
    __shared__ float As[8][128];
    __shared__ float Bs[8][128];

    const int tid = threadIdx.x;
    const int tx = tid & 15;        // 0..15  -> 8 output cols each
    const int ty = tid >> 4;        // 0..15  -> 8 output rows each
    const int bx = blockIdx.x;
    const int by = blockIdx.y;

    float acc[8][8];
#pragma unroll
    for (int i = 0; i < 8; i++)
#pragma unroll
        for (int j = 0; j < 8; j++) acc[i][j] = 0.0f;

    // A-tile loads: 128 rows x 8 cols, one float4 per thread
    const int a_row = tid >> 1;           // 0..127
    const int a_col = (tid & 1) << 2;     // 0 or 4
    // B-tile loads: 8 rows x 128 cols, one float4 per thread
    const int b_row = tid >> 5;           // 0..7
    const int b_col = (tid & 31) << 2;    // 0..124

    const float* Ap = A + (size_t)(by * 128 + a_row) * K + a_col;
    const float* Bp = B + (size_t)b_row * N + bx * 128 + b_col;

    for (int k0 = 0; k0 < K; k0 += 8) {
        float4 av = *(const float4*)(Ap + k0);
        float4 bv = *(const float4*)(Bp + (size_t)k0 * N);
        As[a_col + 0][a_row] = av.x;
        As[a_col + 1][a_row] = av.y;
        As[a_col + 2][a_row] = av.z;
        As[a_col + 3][a_row] = av.w;
        *(float4*)&Bs[b_row][b_col] = bv;
        __syncthreads();

#pragma unroll
        for (int k = 0; k < 8; k++) {
            float ar[8], br[8];
#pragma unroll
            for (int i = 0; i < 8; i++) ar[i] = As[k][ty * 8 + i];
#pragma unroll
            for (int j = 0; j < 8; j++) br[j] = Bs[k][tx * 8 + j];
#pragma unroll
            for (int i = 0; i < 8; i++)
#pragma unroll
                for (int j = 0; j < 8; j++) acc[i][j] += ar[i] * br[j];
        }
        __syncthreads();
    }

#pragma unroll
    for (int i = 0; i < 8; i++) {
        float* Cp = C + (size_t)(by * 128 + ty * 8 + i) * N + bx * 128 + tx * 8;
        *(float4*)Cp       = make_float4(acc[i][0], acc[i][1], acc[i][2], acc[i][3]);
        *(float4*)(Cp + 4) = make_float4(acc[i][4], acc[i][5], acc[i][6], acc[i][7]);
    }
}

// ---------------------------------------------------------------------------
// Fused L2-normalize (over 64-dim head) + RoPE, in place.
// buf layout: [TOKENS, n_heads*64]. One warp per (token, head); lane holds
// dims (lane, lane+32) which is exactly the RoPE half-split pairing.
// ---------------------------------------------------------------------------
__global__ void norm_rope_kernel(float* __restrict__ buf,
                                 const float* __restrict__ cosb,
                                 const float* __restrict__ sinb,
                                 int n_heads)
{
    const int warp = (blockIdx.x * blockDim.x + threadIdx.x) >> 5;
    const int lane = threadIdx.x & 31;
    const int total = TOKENS * n_heads;
    if (warp >= total) return;
    const int token = warp / n_heads;
    const int head  = warp % n_heads;

    float* p = buf + (size_t)token * n_heads * DH + head * DH;
    float x1 = p[lane];
    float x2 = p[lane + 32];
    float ss = x1 * x1 + x2 * x2;
#pragma unroll
    for (int o = 16; o; o >>= 1) ss += __shfl_xor_sync(0xffffffffu, ss, o);
    const float inv = 1.0f / (sqrtf(ss) + 1e-8f);
    x1 *= inv; x2 *= inv;

    const int s = token % S_LEN;           // position within sequence
    const float c  = cosb[s * 32 + lane];
    const float sn = sinb[s * 32 + lane];
    p[lane]      = x1 * c - x2 * sn;
    p[lane + 32] = x1 * sn + x2 * c;
}

// ---------------------------------------------------------------------------
// Sliding-window attention with tanh softcap. One warp = one query (online
// softmax in registers). Block = 8 warps = 8 consecutive queries, sharing
// staged 32-key K/V tiles in shared memory.
// Mask: allowed(q,k) = (k <= q) && (k > q-256 || k < 4)
// Tiles processed: {0} ∪ [floor(max(0,q0-255)/32), floor((q0+7)/32)]
// ---------------------------------------------------------------------------
__global__ __launch_bounds__(256) void attn_kernel()
{
    __shared__ float Kt[DH][33];   // [d][key], padded: conflict-free score reads
    __shared__ float Vs[32][DH];   // [key][d]: conflict-free PV reads
    __shared__ float Qs[8][DH];

    const int tid  = threadIdx.x;
    const int lane = tid & 31;
    const int w    = tid >> 5;     // warp id = query-in-block
    const int b    = blockIdx.z;
    const int h    = blockIdx.y;
    const int q0   = blockIdx.x * 8;
    const int kvh  = h >> 2;       // N_GROUPS = 4
    const int q    = q0 + w;

    // Load Q tile (8 queries x 64 dims)
    for (int i = tid; i < 8 * DH; i += 256) {
        const int r = i >> 6, d = i & 63;
        Qs[r][d] = g_Q[(size_t)(b * S_LEN + q0 + r) * DMODEL + h * DH + d];
    }

    float m = -1e30f, l = 0.0f, acc0 = 0.0f, acc1 = 0.0f;

    int wstart = q0 - 255; if (wstart < 0) wstart = 0;
    const int t0   = wstart >> 5;
    const int tmax = (q0 + 7) >> 5;
    const int ntiles = (tmax - t0 + 1) + (t0 > 0 ? 1 : 0);

    const float* Kbase = g_K + (size_t)b * S_LEN * KVDIM + kvh * DH;
    const float* Vbase = g_V + (size_t)b * S_LEN * KVDIM + kvh * DH;

    for (int ti = 0; ti < ntiles; ti++) {
        const int t  = (t0 > 0) ? (ti == 0 ? 0 : t0 + ti - 1) : ti;
        const int kb = t * 32;

        __syncthreads();
        for (int i = tid; i < 32 * 64; i += 256) {
            const int key = i >> 6, d = i & 63;
            Kt[d][key] = Kbase[(size_t)(kb + key) * KVDIM + d];
            Vs[key][d] = Vbase[(size_t)(kb + key) * KVDIM + d];
        }
        __syncthreads();

        // score for this lane's key
        const int kk = kb + lane;
        float s = 0.0f;
#pragma unroll
        for (int d = 0; d < DH; d++) s += Qs[w][d] * Kt[d][lane];
        s *= 0.125f;                               // ATTN_SCALE = 1/sqrt(64)
        s = 15.0f * tanhf(s * (1.0f / 15.0f));     // logit softcap

        const bool valid = (kk <= q) && ((kk > q - 256) || (kk < 4));
        const float sv = valid ? s : -1e30f;

        // warp-max over tile
        float mt = sv;
#pragma unroll
        for (int o = 16; o; o >>= 1) mt = fmaxf(mt, __shfl_xor_sync(0xffffffffu, mt, o));
        const float m_new = fmaxf(m, mt);          // finite after first tile (key 0 or q valid)
        const float corr  = expf(m - m_new);
        const float p     = expf(sv - m_new);      // masked lanes -> exp(-huge) = 0

        float psum = p;
#pragma unroll
        for (int o = 16; o; o >>= 1) psum += __shfl_xor_sync(0xffffffffu, psum, o);
        l = l * corr + psum;
        acc0 *= corr; acc1 *= corr;

#pragma unroll
        for (int k2 = 0; k2 < 32; k2++) {
            const float pk = __shfl_sync(0xffffffffu, p, k2);
            acc0 += pk * Vs[k2][lane];
            acc1 += pk * Vs[k2][lane + 32];
        }
        m = m_new;
    }

    const float invl = 1.0f / l;
    const size_t o = (size_t)(b * S_LEN + q) * DMODEL + h * DH;
    g_C[o + lane]      = acc0 * invl;
    g_C[o + lane + 32] = acc1 * invl;
}

// ---------------------------------------------------------------------------
extern "C" void kernel_launch(void* const* d_in, const int* in_sizes, int n_in,
                              void* d_out, int out_size)
{
    const float* x    = (const float*)d_in[0];
    const float* cosb = (const float*)d_in[1];
    const float* sinb = (const float*)d_in[2];
    // d_in[3] = mask: reconstructed analytically, unused
    const float* Wq   = (const float*)d_in[4];
    const float* Wk   = (const float*)d_in[5];
    const float* Wv   = (const float*)d_in[6];
    const float* Wo   = (const float*)d_in[7];
    float* out = (float*)d_out;

    float *Qp, *Kp, *Vp, *Cp;
    cudaGetSymbolAddress((void**)&Qp, g_Q);
    cudaGetSymbolAddress((void**)&Kp, g_K);
    cudaGetSymbolAddress((void**)&Vp, g_V);
    cudaGetSymbolAddress((void**)&Cp, g_C);

    // QKV projections
    sgemm128<<<dim3(DMODEL / 128, TOKENS / 128), 256>>>(x, Wq, Qp, TOKENS, DMODEL, DMODEL);
    sgemm128<<<dim3(KVDIM  / 128, TOKENS / 128), 256>>>(x, Wk, Kp, TOKENS, KVDIM,  DMODEL);
    sgemm128<<<dim3(KVDIM  / 128, TOKENS / 128), 256>>>(x, Wv, Vp, TOKENS, KVDIM,  DMODEL);

    // L2-normalize + RoPE (Q and K only)
    norm_rope_kernel<<<(TOKENS * NH)  / 8, 256>>>(Qp, cosb, sinb, NH);
    norm_rope_kernel<<<(TOKENS * NKV) / 8, 256>>>(Kp, cosb, sinb, NKV);

    // Sliding-window attention
    attn_kernel<<<dim3(S_LEN / 8, NH, BATCH), 256>>>();

    // Output projection
    sgemm128<<<dim3(DMODEL / 128, TOKENS / 128), 256>>>(Cp, Wo, out, TOKENS, DMODEL, DMODEL);
}

// round 4
// speedup vs baseline: 1.6545x; 1.6545x over previous
#include <cuda_runtime.h>
#include <cuda_bf16.h>
#include <math.h>

#define S_LEN 2048
#define BATCH 2
#define DMODEL 1024
#define NH 16
#define NKV 4
#define DH 64
#define TOKENS (BATCH * S_LEN)   // 4096
#define KVDIM (NKV * DH)         // 256

// ---------------- scratch (device globals; no allocs allowed) ----------------
__device__ float g_Q[TOKENS * DMODEL];
__device__ float g_K[TOKENS * KVDIM];
__device__ float g_V[TOKENS * KVDIM];
__device__ float g_C[TOKENS * DMODEL];

__device__ __nv_bfloat16 g_Ahi[TOKENS * DMODEL];
__device__ __nv_bfloat16 g_Alo[TOKENS * DMODEL];
__device__ __nv_bfloat16 g_Wqh[DMODEL * DMODEL];
__device__ __nv_bfloat16 g_Wql[DMODEL * DMODEL];
__device__ __nv_bfloat16 g_Wkh[DMODEL * KVDIM];
__device__ __nv_bfloat16 g_Wkl[DMODEL * KVDIM];
__device__ __nv_bfloat16 g_Wvh[DMODEL * KVDIM];
__device__ __nv_bfloat16 g_Wvl[DMODEL * KVDIM];
__device__ __nv_bfloat16 g_Woh[DMODEL * DMODEL];
__device__ __nv_bfloat16 g_Wol[DMODEL * DMODEL];

// ---------------------------------------------------------------------------
// fp32 -> (bf16 hi, bf16 lo) split, vectorized by 4
// ---------------------------------------------------------------------------
__global__ void split_kernel(const float* __restrict__ src,
                             __nv_bfloat16* __restrict__ hi,
                             __nv_bfloat16* __restrict__ lo, int n4)
{
    int i = blockIdx.x * blockDim.x + threadIdx.x;
    if (i >= n4) return;
    float4 v = ((const float4*)src)[i];
    __nv_bfloat16 hx = __float2bfloat16(v.x);
    __nv_bfloat16 hy = __float2bfloat16(v.y);
    __nv_bfloat16 hz = __float2bfloat16(v.z);
    __nv_bfloat16 hw = __float2bfloat16(v.w);
    __nv_bfloat16 lx = __float2bfloat16(v.x - __bfloat162float(hx));
    __nv_bfloat16 ly = __float2bfloat16(v.y - __bfloat162float(hy));
    __nv_bfloat16 lz = __float2bfloat16(v.z - __bfloat162float(hz));
    __nv_bfloat16 lw = __float2bfloat16(v.w - __bfloat162float(hw));
    __nv_bfloat162* H = (__nv_bfloat162*)hi;
    __nv_bfloat162* L = (__nv_bfloat162*)lo;
    H[2 * i]     = __nv_bfloat162(hx, hy);
    H[2 * i + 1] = __nv_bfloat162(hz, hw);
    L[2 * i]     = __nv_bfloat162(lx, ly);
    L[2 * i + 1] = __nv_bfloat162(lz, lw);
}

// ---------------------------------------------------------------------------
// bf16x3 split-precision GEMM via mma.sync m16n8k16.
// C(f32, MxN) = A(MxK) @ B(KxN), A/B given as hi/lo bf16 planes (row-major).
// Block 128x128, 8 warps (2x4), warp tile 64x32, k-step 32.
// ---------------------------------------------------------------------------
__device__ __forceinline__ void mma16816(float* d, const unsigned* a, const unsigned* b)
{
    asm volatile(
        "mma.sync.aligned.m16n8k16.row.col.f32.bf16.bf16.f32 "
        "{%0,%1,%2,%3}, {%4,%5,%6,%7}, {%8,%9}, {%0,%1,%2,%3};\n"
        : "+f"(d[0]), "+f"(d[1]), "+f"(d[2]), "+f"(d[3])
        : "r"(a[0]), "r"(a[1]), "r"(a[2]), "r"(a[3]), "r"(b[0]), "r"(b[1]));
}

#define ASTRIDE 20   // u32 per smem row (32 bf16 data + 8 pad)

__global__ __launch_bounds__(256, 2) void gemm_bf16x3(
    const __nv_bfloat16* __restrict__ Ah, const __nv_bfloat16* __restrict__ Al,
    const __nv_bfloat16* __restrict__ Bh, const __nv_bfloat16* __restrict__ Bl,
    float* __restrict__ C, int M, int N, int K)
{
    __shared__ __align__(16) unsigned As[2][128 * ASTRIDE];   // [plane][row*20+kpair]
    __shared__ __align__(16) unsigned Bt[2][128 * ASTRIDE];   // [plane][col*20+kpair]

    const int tid = threadIdx.x;
    const int lane = tid & 31, w = tid >> 5;
    const int bm = blockIdx.y * 128, bn = blockIdx.x * 128;
    const int wm = (w >> 2) * 64, wn = (w & 3) * 32;
    const int lr = lane >> 2, lc = lane & 3;

    float acc[4][4][4];
#pragma unroll
    for (int i = 0; i < 4; i++)
#pragma unroll
        for (int j = 0; j < 4; j++)
#pragma unroll
            for (int r = 0; r < 4; r++) acc[i][j][r] = 0.0f;

    const int bkp = tid & 15, bcg = tid >> 4;   // B-loader coords

    for (int k0 = 0; k0 < K; k0 += 32) {
        __syncthreads();
        // ---- load A tile (128x32, both planes), uint4 = 8 bf16 ----
#pragma unroll
        for (int half = 0; half < 2; half++) {
            int i = tid + half * 256;          // 0..511
            int row = i >> 2, v = i & 3;
            size_t go = (size_t)(bm + row) * K + k0 + v * 8;
            uint4 dh = *(const uint4*)(Ah + go);
            uint4 dl = *(const uint4*)(Al + go);
            *(uint4*)&As[0][row * ASTRIDE + v * 4] = dh;
            *(uint4*)&As[1][row * ASTRIDE + v * 4] = dl;
        }
        // ---- load B tile transposed: Bt[col][kpair] packs (k,k+1) ----
        {
            size_t o0 = (size_t)(k0 + 2 * bkp) * N + bn + bcg * 8;
            uint4 r0h = *(const uint4*)(Bh + o0);
            uint4 r1h = *(const uint4*)(Bh + o0 + N);
            uint4 r0l = *(const uint4*)(Bl + o0);
            uint4 r1l = *(const uint4*)(Bl + o0 + N);
            const unsigned short* a0 = (const unsigned short*)&r0h;
            const unsigned short* a1 = (const unsigned short*)&r1h;
            const unsigned short* c0 = (const unsigned short*)&r0l;
            const unsigned short* c1 = (const unsigned short*)&r1l;
#pragma unroll
            for (int j = 0; j < 8; j++) {
                Bt[0][(bcg * 8 + j) * ASTRIDE + bkp] = (unsigned)a0[j] | ((unsigned)a1[j] << 16);
                Bt[1][(bcg * 8 + j) * ASTRIDE + bkp] = (unsigned)c0[j] | ((unsigned)c1[j] << 16);
            }
        }
        __syncthreads();

#pragma unroll
        for (int ks = 0; ks < 2; ks++) {
            const int kb = ks * 8;
            unsigned bh[4][2], bl[4][2];
#pragma unroll
            for (int nt = 0; nt < 4; nt++) {
                int n = wn + nt * 8 + lr;
                bh[nt][0] = Bt[0][n * ASTRIDE + kb + lc];
                bh[nt][1] = Bt[0][n * ASTRIDE + kb + 4 + lc];
                bl[nt][0] = Bt[1][n * ASTRIDE + kb + lc];
                bl[nt][1] = Bt[1][n * ASTRIDE + kb + 4 + lc];
            }
#pragma unroll
            for (int mt = 0; mt < 4; mt++) {
                int r = wm + mt * 16 + lr;
                unsigned ah[4], al[4];
                ah[0] = As[0][r * ASTRIDE + kb + lc];
                ah[1] = As[0][(r + 8) * ASTRIDE + kb + lc];
                ah[2] = As[0][r * ASTRIDE + kb + 4 + lc];
                ah[3] = As[0][(r + 8) * ASTRIDE + kb + 4 + lc];
                al[0] = As[1][r * ASTRIDE + kb + lc];
                al[1] = As[1][(r + 8) * ASTRIDE + kb + lc];
                al[2] = As[1][r * ASTRIDE + kb + 4 + lc];
                al[3] = As[1][(r + 8) * ASTRIDE + kb + 4 + lc];
#pragma unroll
                for (int nt = 0; nt < 4; nt++) {
                    mma16816(acc[mt][nt], ah, bh[nt]);   // hi*hi
                    mma16816(acc[mt][nt], ah, bl[nt]);   // hi*lo
                    mma16816(acc[mt][nt], al, bh[nt]);   // lo*hi
                }
            }
        }
    }

    // ---- epilogue ----
#pragma unroll
    for (int mt = 0; mt < 4; mt++)
#pragma unroll
        for (int nt = 0; nt < 4; nt++) {
            int r = bm + wm + mt * 16 + lr;
            int cN = bn + wn + nt * 8 + 2 * lc;
            *(float2*)&C[(size_t)r * N + cN] = make_float2(acc[mt][nt][0], acc[mt][nt][1]);
            *(float2*)&C[(size_t)(r + 8) * N + cN] = make_float2(acc[mt][nt][2], acc[mt][nt][3]);
        }
}

// ---------------------------------------------------------------------------
// Fused L2-normalize (64-dim head) + RoPE, in place.
// ---------------------------------------------------------------------------
__global__ void norm_rope_kernel(float* __restrict__ buf,
                                 const float* __restrict__ cosb,
                                 const float* __restrict__ sinb,
                                 int n_heads)
{
    const int warp = (blockIdx.x * blockDim.x + threadIdx.x) >> 5;
    const int lane = threadIdx.x & 31;
    const int total = TOKENS * n_heads;
    if (warp >= total) return;
    const int token = warp / n_heads;
    const int head  = warp % n_heads;

    float* p = buf + (size_t)token * n_heads * DH + head * DH;
    float x1 = p[lane];
    float x2 = p[lane + 32];
    float ss = x1 * x1 + x2 * x2;
#pragma unroll
    for (int o = 16; o; o >>= 1) ss += __shfl_xor_sync(0xffffffffu, ss, o);
    const float inv = 1.0f / (sqrtf(ss) + 1e-8f);
    x1 *= inv; x2 *= inv;

    const int s = token % S_LEN;
    const float c  = cosb[s * 32 + lane];
    const float sn = sinb[s * 32 + lane];
    p[lane]      = x1 * c - x2 * sn;
    p[lane + 32] = x1 * sn + x2 * c;
}

// ---------------------------------------------------------------------------
// Sliding-window attention. 2 queries per warp, Q fully register-resident.
// Block = 8 warps = 16 consecutive queries; 32-key K/V tiles in smem.
// allowed(q,k) = (k <= q) && (k > q-256 || k < 4)
// ---------------------------------------------------------------------------
__device__ __forceinline__ float tanh_fast(float x)
{
    float y;
    asm("tanh.approx.f32 %0, %1;" : "=f"(y) : "f"(x));
    return y;
}

__global__ __launch_bounds__(256) void attn2_kernel()
{
    __shared__ float Kt[DH][33];    // [d][key]
    __shared__ float Vs[32][DH];    // [key][d]

    const int tid  = threadIdx.x;
    const int lane = tid & 31;
    const int w    = tid >> 5;
    const int b    = blockIdx.z;
    const int h    = blockIdx.y;
    const int q0   = blockIdx.x * 16;
    const int kvh  = h >> 2;
    const int q1   = q0 + 2 * w;
    const int q2   = q1 + 1;

    // Q for both queries in registers (broadcast loads; L1-served)
    float qa[DH], qb[DH];
    const float* Qp = g_Q + (size_t)(b * S_LEN + q1) * DMODEL + h * DH;
#pragma unroll
    for (int d = 0; d < DH; d++) { qa[d] = Qp[d]; qb[d] = Qp[DMODEL + d]; }

    float m1 = -1e30f, l1 = 0.0f, m2 = -1e30f, l2 = 0.0f;
    float a1x = 0.0f, a1y = 0.0f, a2x = 0.0f, a2y = 0.0f;

    int wstart = q0 - 255; if (wstart < 0) wstart = 0;
    const int t0   = wstart >> 5;
    const int tmax = (q0 + 15) >> 5;
    const int ntiles = (tmax - t0 + 1) + (t0 > 0 ? 1 : 0);

    const float* Kbase = g_K + (size_t)b * S_LEN * KVDIM + kvh * DH;
    const float* Vbase = g_V + (size_t)b * S_LEN * KVDIM + kvh * DH;

    for (int ti = 0; ti < ntiles; ti++) {
        const int t  = (t0 > 0) ? (ti == 0 ? 0 : t0 + ti - 1) : ti;
        const int kb = t * 32;

        __syncthreads();
#pragma unroll
        for (int it = 0; it < 2; it++) {
            int i = tid + it * 256;           // float4 index, 0..511
            int key = i >> 4;
            int d4 = (i & 15) * 4;
            float4 kv = *(const float4*)(Kbase + (size_t)(kb + key) * KVDIM + d4);
            float4 vv = *(const float4*)(Vbase + (size_t)(kb + key) * KVDIM + d4);
            Kt[d4 + 0][key] = kv.x; Kt[d4 + 1][key] = kv.y;
            Kt[d4 + 2][key] = kv.z; Kt[d4 + 3][key] = kv.w;
            *(float4*)&Vs[key][d4] = vv;
        }
        __syncthreads();

        const int kk = kb + lane;
        float s1 = 0.0f, s2 = 0.0f;
#pragma unroll
        for (int d = 0; d < DH; d++) {
            float kt = Kt[d][lane];
            s1 += qa[d] * kt;
            s2 += qb[d] * kt;
        }
        // scale 0.125, softcap 15*tanh(x/15); logits are tiny (|qk|<=1)
        s1 = 15.0f * tanh_fast(s1 * (0.125f / 15.0f));
        s2 = 15.0f * tanh_fast(s2 * (0.125f / 15.0f));

        const bool v1 = (kk <= q1) && ((kk > q1 - 256) || (kk < 4));
        const bool v2 = (kk <= q2) && ((kk > q2 - 256) || (kk < 4));
        float sv1 = v1 ? s1 : -1e30f;
        float sv2 = v2 ? s2 : -1e30f;

        float mt1 = sv1, mt2 = sv2;
#pragma unroll
        for (int o = 16; o; o >>= 1) {
            mt1 = fmaxf(mt1, __shfl_xor_sync(0xffffffffu, mt1, o));
            mt2 = fmaxf(mt2, __shfl_xor_sync(0xffffffffu, mt2, o));
        }
        const float n1 = fmaxf(m1, mt1), n2 = fmaxf(m2, mt2);
        const float c1 = __expf(m1 - n1), c2 = __expf(m2 - n2);
        const float p1 = __expf(sv1 - n1), p2 = __expf(sv2 - n2);
        float ps1 = p1, ps2 = p2;
#pragma unroll
        for (int o = 16; o; o >>= 1) {
            ps1 += __shfl_xor_sync(0xffffffffu, ps1, o);
            ps2 += __shfl_xor_sync(0xffffffffu, ps2, o);
        }
        l1 = l1 * c1 + ps1; l2 = l2 * c2 + ps2;
        a1x *= c1; a1y *= c1; a2x *= c2; a2y *= c2;
        m1 = n1; m2 = n2;

#pragma unroll
        for (int k2 = 0; k2 < 32; k2++) {
            const float pp1 = __shfl_sync(0xffffffffu, p1, k2);
            const float pp2 = __shfl_sync(0xffffffffu, p2, k2);
            const float2 vv = *(const float2*)&Vs[k2][2 * lane];
            a1x += pp1 * vv.x; a1y += pp1 * vv.y;
            a2x += pp2 * vv.x; a2y += pp2 * vv.y;
        }
    }

    const float i1 = 1.0f / l1, i2 = 1.0f / l2;
    const size_t o1 = (size_t)(b * S_LEN + q1) * DMODEL + h * DH;
    *(float2*)&g_C[o1 + 2 * lane]          = make_float2(a1x * i1, a1y * i1);
    *(float2*)&g_C[o1 + DMODEL + 2 * lane] = make_float2(a2x * i2, a2y * i2);
}

// ---------------------------------------------------------------------------
extern "C" void kernel_launch(void* const* d_in, const int* in_sizes, int n_in,
                              void* d_out, int out_size)
{
    const float* x    = (const float*)d_in[0];
    const float* cosb = (const float*)d_in[1];
    const float* sinb = (const float*)d_in[2];
    // d_in[3] = mask: reconstructed analytically, unused
    const float* Wq   = (const float*)d_in[4];
    const float* Wk   = (const float*)d_in[5];
    const float* Wv   = (const float*)d_in[6];
    const float* Wo   = (const float*)d_in[7];
    float* out = (float*)d_out;

    float *Qp, *Kp, *Vp, *Cp;
    __nv_bfloat16 *Ahi, *Alo, *Wqh, *Wql, *Wkh, *Wkl, *Wvh, *Wvl, *Woh, *Wol;
    cudaGetSymbolAddress((void**)&Qp, g_Q);
    cudaGetSymbolAddress((void**)&Kp, g_K);
    cudaGetSymbolAddress((void**)&Vp, g_V);
    cudaGetSymbolAddress((void**)&Cp, g_C);
    cudaGetSymbolAddress((void**)&Ahi, g_Ahi);
    cudaGetSymbolAddress((void**)&Alo, g_Alo);
    cudaGetSymbolAddress((void**)&Wqh, g_Wqh);
    cudaGetSymbolAddress((void**)&Wql, g_Wql);
    cudaGetSymbolAddress((void**)&Wkh, g_Wkh);
    cudaGetSymbolAddress((void**)&Wkl, g_Wkl);
    cudaGetSymbolAddress((void**)&Wvh, g_Wvh);
    cudaGetSymbolAddress((void**)&Wvl, g_Wvl);
    cudaGetSymbolAddress((void**)&Woh, g_Woh);
    cudaGetSymbolAddress((void**)&Wol, g_Wol);

    const int n4x  = TOKENS * DMODEL / 4;   // 1048576
    const int n4q  = DMODEL * DMODEL / 4;   // 262144
    const int n4kv = DMODEL * KVDIM / 4;    // 65536

    // splits
    split_kernel<<<(n4x + 255) / 256, 256>>>(x, Ahi, Alo, n4x);
    split_kernel<<<(n4q + 255) / 256, 256>>>(Wq, Wqh, Wql, n4q);
    split_kernel<<<(n4kv + 255) / 256, 256>>>(Wk, Wkh, Wkl, n4kv);
    split_kernel<<<(n4kv + 255) / 256, 256>>>(Wv, Wvh, Wvl, n4kv);
    split_kernel<<<(n4q + 255) / 256, 256>>>(Wo, Woh, Wol, n4q);

    // QKV projections (tensor cores, bf16x3)
    gemm_bf16x3<<<dim3(DMODEL / 128, TOKENS / 128), 256>>>(Ahi, Alo, Wqh, Wql, Qp, TOKENS, DMODEL, DMODEL);
    gemm_bf16x3<<<dim3(KVDIM  / 128, TOKENS / 128), 256>>>(Ahi, Alo, Wkh, Wkl, Kp, TOKENS, KVDIM,  DMODEL);
    gemm_bf16x3<<<dim3(KVDIM  / 128, TOKENS / 128), 256>>>(Ahi, Alo, Wvh, Wvl, Vp, TOKENS, KVDIM,  DMODEL);

    // L2-normalize + RoPE
    norm_rope_kernel<<<(TOKENS * NH)  / 8, 256>>>(Qp, cosb, sinb, NH);
    norm_rope_kernel<<<(TOKENS * NKV) / 8, 256>>>(Kp, cosb, sinb, NKV);

    // attention
    attn2_kernel<<<dim3(S_LEN / 16, NH, BATCH), 256>>>();

    // output projection
    split_kernel<<<(n4x + 255) / 256, 256>>>(Cp, Ahi, Alo, n4x);
    gemm_bf16x3<<<dim3(DMODEL / 128, TOKENS / 128), 256>>>(Ahi, Alo, Woh, Wol, out, TOKENS, DMODEL, DMODEL);
}